// round 17
// baseline (speedup 1.0000x reference)
#include <cuda_runtime.h>
#include <cuda_fp16.h>
#include <cstdint>

#define Bn   8
#define Cin  64
#define Hh   128
#define Ww   128
#define HW   (Hh*Ww)
#define Cout 64
#define CIN2 66
#define KDIM 594    // CIN2 * 9
#define NCH  5      // 4 chunks x 144 k (16 ch) + 1 tail chunk (2 ch -> 2 ksteps)
#define RS   136    // cols row stride in halves (272 B -> conflict-free ldmatrix)
#define BUFH (144*RS)
#define NKS  38     // 4*9 + 2 ksteps

// ---------------- scratch ----------------
__device__ uint2 g_wfrag   [NKS*8*32];   // main weight fragments, N=64
__device__ uint2 g_wfrag_om[NKS*4*32];   // om weight fragments,   N=27 (pad 32)
__device__ float g_inp_t   [Bn*HW*Cin];  // NHWC transposed input

__global__ void prep_wfrag_kernel(const float* __restrict__ w,
                                  const float* __restrict__ w_om)
{
    int i = blockIdx.x * 256 + threadIdx.x;
    const int main_total = NKS * 256;
    if (i < main_total) {
        int kstep = i >> 8, rem = i & 255;
        int nfrag = rem >> 5, lane = rem & 31;
        int n  = nfrag * 8 + (lane >> 2);
        int kb = kstep * 16 + (lane & 3) * 2;
        auto B = [&](int k) -> uint32_t {
            float v = (k < KDIM) ? w[n * KDIM + k] : 0.0f;
            return (uint32_t)__half_as_ushort(__float2half_rn(v));
        };
        g_wfrag[i] = make_uint2(B(kb) | (B(kb+1) << 16), B(kb+8) | (B(kb+9) << 16));
    } else if (i < main_total + NKS * 128) {
        int j = i - main_total;
        int kstep = j >> 7, rem = j & 127;
        int nfrag = rem >> 5, lane = rem & 31;
        int n  = nfrag * 8 + (lane >> 2);
        int kb = kstep * 16 + (lane & 3) * 2;
        auto B = [&](int k) -> uint32_t {
            float v = (n < 27 && k < KDIM) ? w_om[n * KDIM + k] : 0.0f;
            return (uint32_t)__half_as_ushort(__float2half_rn(v));
        };
        g_wfrag_om[j] = make_uint2(B(kb) | (B(kb+1) << 16), B(kb+8) | (B(kb+9) << 16));
    }
}

// NCHW -> NHWC transpose, one block per (h row, batch); smem tiled, both
// global accesses coalesced, smem column reads conflict-free (stride 129).
__global__ void __launch_bounds__(256) transpose_kernel(const float* __restrict__ in)
{
    __shared__ float t[Cin][129];
    const int h = blockIdx.x;
    const int b = blockIdx.y;
    const int tid = threadIdx.x;
    for (int i = tid; i < Cin * Ww; i += 256) {
        int c = i >> 7, w = i & 127;
        t[c][w] = in[((b * Cin + c) * Hh + h) * Ww + w];
    }
    __syncthreads();
    float* dst = g_inp_t + ((size_t)b * HW + (size_t)h * Ww) * Cin;
    for (int i = tid; i < Ww * Cin; i += 256) {
        int w = i >> 6, c = i & 63;
        dst[w * Cin + c] = t[c][w];
    }
}

__device__ __forceinline__ uint32_t smem_u32(const void* p) {
    uint32_t a;
    asm("{ .reg .u64 t; cvta.to.shared.u64 t, %1; cvt.u32.u64 %0, t; }"
        : "=r"(a) : "l"(p));
    return a;
}

// ---------------- fused kernel ----------------
// One block per (row y, batch b); 384 threads.
// Phase B: om conv via mma (producers fill regular im2col from NCHW input).
// Phase C: packed corner tables.
// Phase D: deformable gather from NHWC g_inp_t (float4 channel-vectorized) + mma.
// Smem bytes: sWt[0,18432) sPk[18432,23040) cols[23040,101376)
//             ombo[101376,105984) ombm[105984,110592)
__global__ void __launch_bounds__(384, 2) fused_kernel(
    const float* __restrict__ input,
    const float* __restrict__ b_om,
    const float* __restrict__ bias,
    float* __restrict__ out,
    float* __restrict__ idx_out,
    float* __restrict__ mask_out)
{
    extern __shared__ float sm[];
    float4* sWt  = (float4*)sm;               // [1152]
    int*    sPk  = (int*)(sm + 4608);         // [1152]
    __half* cols = (__half*)(sm + 5760);      // [2][144][136]
    __half* ombo = (__half*)(sm + 25344);     // [18][128] offsets
    float*  ombm = sm + 26496;                // [9][128]  mask

    const int tid = threadIdx.x;
    const int y   = blockIdx.x;
    const int b   = blockIdx.y;
    const float inv = 1.0f / 128.0f;

    const int lane = tid & 31;
    const uint32_t cbase = smem_u32(cols);
    const int m0   = (tid >> 5) * 16;
    const int r    = lane & 7;
    const int kofs = (lane & 16) ? 8 : 0;
    const int mofs = (lane & 8)  ? 8 : 0;
    const uint32_t off0 = (uint32_t)(((kofs + r) * RS + m0 + mofs) * 2);

    const float* binp = input + b * Cin * HW;

    // ================= phase B: om conv via mma =================
    if (tid >= 256) {
        // producers: regular im2col fill (shifted rows from NCHW), 16 ch/chunk
        const int ptid = tid - 256;   // pixel

        auto produce_om = [&](int cn, int buf) {
            __half* dst = cols + buf * BUFH + ptid;
            if (cn < 4) {
#pragma unroll
                for (int cc = 0; cc < 16; cc++) {
                    const float* base = binp + (16 * cn + cc) * HW;
#pragma unroll
                    for (int dy = 0; dy < 3; dy++) {
                        int yy = y + dy - 1;
                        bool yok = (yy >= 0 && yy < Hh);
                        const float* rp = base + yy * Ww;
#pragma unroll
                        for (int dx = 0; dx < 3; dx++) {
                            int xx = ptid + dx - 1;
                            float v = (yok && xx >= 0 && xx < Ww) ? rp[xx] : 0.0f;
                            dst[(cc * 9 + dy * 3 + dx) * RS] = __float2half_rn(v);
                        }
                    }
                }
            } else {
                // ch 64 = h-coord, ch 65 = w-coord (conv zero padding!)
#pragma unroll
                for (int dy = 0; dy < 3; dy++) {
                    int yy = y + dy - 1;
                    bool yok = (yy >= 0 && yy < Hh);
#pragma unroll
                    for (int dx = 0; dx < 3; dx++) {
                        int xx = ptid + dx - 1;
                        bool ok = yok && xx >= 0 && xx < Ww;
                        dst[(dy * 3 + dx) * RS] =
                            __float2half_rn(ok ? yy * inv : 0.0f);
                        dst[(9 + dy * 3 + dx) * RS] =
                            __float2half_rn(ok ? xx * inv - 0.5f : 0.0f);
                    }
                }
#pragma unroll
                for (int s = 18; s < 32; s++) dst[s * RS] = __ushort_as_half(0);
            }
        };

        produce_om(0, 0);
        __syncthreads();
        for (int c = 0; c < NCH; c++) {
            if (c + 1 < NCH) produce_om(c + 1, (c + 1) & 1);
            __syncthreads();
        }
    } else {
        // consumers: mma vs om fragments; warp = 16 px x 32 oc
        float dacc[4][4];
#pragma unroll
        for (int i = 0; i < 4; i++)
#pragma unroll
            for (int j = 0; j < 4; j++) dacc[i][j] = 0.0f;

        __syncthreads();
        for (int c = 0; c < NCH; c++) {
            const uint32_t bufa = cbase + (uint32_t)((c & 1) * (BUFH * 2)) + off0;
            const int nks = (c < 4) ? 9 : 2;
            for (int ks = 0; ks < nks; ks++) {
                uint32_t a0, a1, a2, a3;
                uint32_t addr = bufa + (uint32_t)(ks * 16 * RS * 2);
                asm volatile(
                    "ldmatrix.sync.aligned.m8n8.x4.trans.shared.b16 "
                    "{%0,%1,%2,%3}, [%4];"
                    : "=r"(a0), "=r"(a1), "=r"(a2), "=r"(a3) : "r"(addr));
                const uint2* wfp = g_wfrag_om + (c * 9 + ks) * 128 + lane;
#pragma unroll
                for (int nf = 0; nf < 4; nf++) {
                    uint2 bv = __ldg(wfp + nf * 32);
                    asm volatile(
                        "mma.sync.aligned.m16n8k16.row.col.f32.f16.f16.f32 "
                        "{%0,%1,%2,%3}, {%4,%5,%6,%7}, {%8,%9}, {%0,%1,%2,%3};"
                        : "+f"(dacc[nf][0]), "+f"(dacc[nf][1]),
                          "+f"(dacc[nf][2]), "+f"(dacc[nf][3])
                        : "r"(a0), "r"(a1), "r"(a2), "r"(a3),
                          "r"(bv.x), "r"(bv.y));
                }
            }
            __syncthreads();
        }

        // writeback om results
        const int m  = lane >> 2;
        const int np = (lane & 3) * 2;
        const int pix0 = m0 + m, pix1 = m0 + m + 8;
#pragma unroll
        for (int nf = 0; nf < 4; nf++) {
#pragma unroll
            for (int h = 0; h < 2; h++) {
                int oc = nf * 8 + np + h;
                if (oc >= 27) continue;
                float bv = __ldg(b_om + oc);
                float a0 = dacc[nf][h]     + bv;
                float a1 = dacc[nf][2 + h] + bv;
                if (oc < 18) {
                    ombo[oc * 128 + pix0] = __float2half_rn(a0);
                    ombo[oc * 128 + pix1] = __float2half_rn(a1);
                    float b0, b1;
                    if (oc < 9) {
                        b0 = b1 = y * inv + (float)(oc / 3 - 1);
                    } else {
                        float cc = -0.5f + (float)((oc - 9) % 3 - 1);
                        b0 = pix0 * inv + cc;
                        b1 = pix1 * inv + cc;
                    }
                    float* ip = idx_out + ((b * 18 + oc) * Hh + y) * Ww;
                    ip[pix0] = b0 + a0;
                    ip[pix1] = b1 + a1;
                } else {
                    float s0 = 1.0f / (1.0f + __expf(-a0));
                    float s1 = 1.0f / (1.0f + __expf(-a1));
                    ombm[(oc - 18) * 128 + pix0] = s0;
                    ombm[(oc - 18) * 128 + pix1] = s1;
                    float* mp = mask_out + ((b * 9 + oc - 18) * Hh + y) * Ww;
                    mp[pix0] = s0;
                    mp[pix1] = s1;
                }
            }
        }
    }
    __syncthreads();

    // ================= phase C: packed corner tables =================
    for (int q = tid; q < 9 * 128; q += 384) {
        int t = q >> 7;
        int p = q & 127;
        float oh = __half2float(ombo[(2 * t) * 128 + p]);
        float ow = __half2float(ombo[(2 * t + 1) * 128 + p]);
        float mk = ombm[t * 128 + p];

        float ph = oh + (float)(t / 3) + (float)(y - 1);
        float pw = ow + (float)(t % 3) + (float)(p - 1);
        float h0f = floorf(ph), w0f = floorf(pw);
        float lh = ph - h0f, lw = pw - w0f;
        float hh = 1.0f - lh, hw = 1.0f - lw;
        int h0 = (int)h0f, w0 = (int)w0f;
        int h1 = h0 + 1,   w1 = w0 + 1;
        float okh0 = (h0 >= 0 && h0 < Hh) ? 1.0f : 0.0f;
        float okh1 = (h1 >= 0 && h1 < Hh) ? 1.0f : 0.0f;
        float okw0 = (w0 >= 0 && w0 < Ww) ? 1.0f : 0.0f;
        float okw1 = (w1 >= 0 && w1 < Ww) ? 1.0f : 0.0f;
        float w00 = hh * hw * okh0 * okw0 * mk;
        float w01 = hh * lw * okh0 * okw1 * mk;
        float w10 = lh * hw * okh1 * okw0 * mk;
        float w11 = lh * lw * okh1 * okw1 * mk;
        int h0c = min(max(h0, 0), Hh - 1), h1c = min(max(h1, 0), Hh - 1);
        int w0c = min(max(w0, 0), Ww - 1), w1c = min(max(w1, 0), Ww - 1);

        sWt[q] = make_float4(w00, w01, w10, w11);
        sPk[q] = (h0c * 128 + w0c) | ((h1c - h0c) << 14) | ((w1c - w0c) << 15);
    }
    __syncthreads();

    // ================= phase D: deformable gather (NHWC) + mma =================
    if (tid >= 256) {
        // producers: one pixel per thread; 16 channels per chunk, float4 loads
        const int ptid = tid - 256;
        const float* bt = g_inp_t + (size_t)b * HW * Cin;

        auto produce = [&](int cn, int buf) {
            __half* dst = cols + buf * BUFH + ptid;
            if (cn < 4) {
                const int c0 = 16 * cn;
#pragma unroll
                for (int t = 0; t < 9; t++) {
                    int    pk = sPk[t * 128 + ptid];
                    float4 wt = sWt[t * 128 + ptid];
                    int a00 = pk & 0x3FFF;                  // pixel index
                    int a10 = a00 + ((pk & 0x4000) >> 7);   // +128 px if dh
                    int dw  = (pk >> 15) & 1;
                    const float* p00 = bt + a00 * Cin + c0;
                    const float* p01 = p00 + dw * Cin;
                    const float* p10 = bt + a10 * Cin + c0;
                    const float* p11 = p10 + dw * Cin;
#pragma unroll
                    for (int j = 0; j < 4; j++) {
                        float4 c00 = *reinterpret_cast<const float4*>(p00 + j * 4);
                        float4 c01 = *reinterpret_cast<const float4*>(p01 + j * 4);
                        float4 c10 = *reinterpret_cast<const float4*>(p10 + j * 4);
                        float4 c11 = *reinterpret_cast<const float4*>(p11 + j * 4);
                        float v0 = wt.x*c00.x + wt.y*c01.x + wt.z*c10.x + wt.w*c11.x;
                        float v1 = wt.x*c00.y + wt.y*c01.y + wt.z*c10.y + wt.w*c11.y;
                        float v2 = wt.x*c00.z + wt.y*c01.z + wt.z*c10.z + wt.w*c11.z;
                        float v3 = wt.x*c00.w + wt.y*c01.w + wt.z*c10.w + wt.w*c11.w;
                        dst[((j * 4 + 0) * 9 + t) * RS] = __float2half_rn(v0);
                        dst[((j * 4 + 1) * 9 + t) * RS] = __float2half_rn(v1);
                        dst[((j * 4 + 2) * 9 + t) * RS] = __float2half_rn(v2);
                        dst[((j * 4 + 3) * 9 + t) * RS] = __float2half_rn(v3);
                    }
                }
            } else {
                // tail: deformed coordinate channels + zero pad
#pragma unroll
                for (int t = 0; t < 9; t++) {
                    int    pk = sPk[t * 128 + ptid];
                    float4 wt = sWt[t * 128 + ptid];
                    int a00 = pk & 0x3FFF;
                    float h0c = (float)(a00 >> 7), w0c = (float)(a00 & 127);
                    float h1c = h0c + (float)((pk >> 14) & 1);
                    float w1c = w0c + (float)((pk >> 15) & 1);
                    dst[t * RS] = __float2half_rn(
                        ((wt.x + wt.y) * h0c + (wt.z + wt.w) * h1c) * inv);
                    dst[(9 + t) * RS] = __float2half_rn(
                          (wt.x + wt.z) * (w0c * inv - 0.5f)
                        + (wt.y + wt.w) * (w1c * inv - 0.5f));
                }
#pragma unroll
                for (int s = 18; s < 32; s++) dst[s * RS] = __ushort_as_half(0);
            }
        };

        produce(0, 0);
        __syncthreads();
        for (int c = 0; c < NCH; c++) {
            if (c + 1 < NCH) produce(c + 1, (c + 1) & 1);
            __syncthreads();
        }
    } else {
        // consumers: mma m16n8k16; warp = 16 px x 64 oc
        float dacc[8][4];
#pragma unroll
        for (int i = 0; i < 8; i++)
#pragma unroll
            for (int j = 0; j < 4; j++) dacc[i][j] = 0.0f;

        __syncthreads();
        for (int c = 0; c < NCH; c++) {
            const uint32_t bufa = cbase + (uint32_t)((c & 1) * (BUFH * 2)) + off0;
            const int nks = (c < 4) ? 9 : 2;
            for (int ks = 0; ks < nks; ks++) {
                uint32_t a0, a1, a2, a3;
                uint32_t addr = bufa + (uint32_t)(ks * 16 * RS * 2);
                asm volatile(
                    "ldmatrix.sync.aligned.m8n8.x4.trans.shared.b16 "
                    "{%0,%1,%2,%3}, [%4];"
                    : "=r"(a0), "=r"(a1), "=r"(a2), "=r"(a3) : "r"(addr));
                const uint2* wfp = g_wfrag + (c * 9 + ks) * 256 + lane;
#pragma unroll
                for (int nf = 0; nf < 8; nf++) {
                    uint2 bv = __ldg(wfp + nf * 32);
                    asm volatile(
                        "mma.sync.aligned.m16n8k16.row.col.f32.f16.f16.f32 "
                        "{%0,%1,%2,%3}, {%4,%5,%6,%7}, {%8,%9}, {%0,%1,%2,%3};"
                        : "+f"(dacc[nf][0]), "+f"(dacc[nf][1]),
                          "+f"(dacc[nf][2]), "+f"(dacc[nf][3])
                        : "r"(a0), "r"(a1), "r"(a2), "r"(a3),
                          "r"(bv.x), "r"(bv.y));
                }
            }
            __syncthreads();
        }

        // writeback
        const int m  = lane >> 2;
        const int np = (lane & 3) * 2;
#pragma unroll
        for (int nf = 0; nf < 8; nf++) {
            int oc = nf * 8 + np;
            float b0v = __ldg(bias + oc);
            float b1v = __ldg(bias + oc + 1);
            float* o0 = out + ((b * Cout + oc)     * Hh + y) * Ww;
            float* o1 = out + ((b * Cout + oc + 1) * Hh + y) * Ww;
            o0[m0 + m]     = dacc[nf][0] + b0v;
            o1[m0 + m]     = dacc[nf][1] + b1v;
            o0[m0 + m + 8] = dacc[nf][2] + b0v;
            o1[m0 + m + 8] = dacc[nf][3] + b1v;
        }
    }
}

// ---------------- launcher ----------------
extern "C" void kernel_launch(void* const* d_in, const int* in_sizes, int n_in,
                              void* d_out, int out_size)
{
    const float* input  = (const float*)d_in[0];
    const float* weight = (const float*)d_in[1];
    const float* bias   = (const float*)d_in[2];
    const float* w_om   = (const float*)d_in[3];
    const float* b_om   = (const float*)d_in[4];

    float* out      = (float*)d_out;
    float* idx_out  = out + (size_t)Bn * Cout * Hh * Ww;
    float* mask_out = idx_out + (size_t)Bn * 18 * Hh * Ww;

    const int smF = 110592;
    cudaFuncSetAttribute(fused_kernel, cudaFuncAttributeMaxDynamicSharedMemorySize, smF);

    prep_wfrag_kernel<<<(NKS * 256 + NKS * 128 + 255) / 256, 256>>>(weight, w_om);
    transpose_kernel<<<dim3(Hh, Bn), 256>>>(input);
    fused_kernel<<<dim3(Hh, Bn), 384, smF>>>(input, b_om, bias,
                                             out, idx_out, mask_out);
}